// round 10
// baseline (speedup 1.0000x reference)
#include <cuda_runtime.h>
#include <math.h>

// YOLO loss — single fused launch, multi-tile double-buffered cp.async
// pipeline. pred/tcls/tbox all staged to smem (tcls+tbox mask-predicated).
// Outputs 5 f32: total, reg, containing, noobj, cls.

#define S_GRID_INV (1.0f / 14.0f)
#define L_COORD 5.0f
#define L_NOOBJ 0.5f
#define TPB 256
#define NWARP (TPB / 32)
#define CPW 64                    // cells per warp per tile
#define CPB (NWARP * CPW)         // 512 cells per block-tile
#define PRED_FL (CPW * 30)        // 1920 floats
#define TCLS_FL (CPW * 20)        // 1280 floats
#define TBOX_FL (CPW * 4)         // 256 floats
#define BUF_FL  (PRED_FL + TCLS_FL + TBOX_FL)   // 3456 floats = 13824 B
#define RED_FL  64                // reduction scratch at smem start
#define SMEM_FLOATS (RED_FL + NWARP * 2 * BUF_FL)
#define SMEM_BYTES (SMEM_FLOATS * 4)            // 221,440 B

__device__ double g_acc[4];      // cls, noobj(raw), reg(raw), containing
__device__ unsigned g_counter;   // zero-init; reset by last block each run

extern __shared__ float dynsmem[];

struct MaskPair { bool m0, m1; };

__device__ __forceinline__ MaskPair loadMasks(const void* maskv, int mode,
                                              int cell0, int lane, int ncell) {
    MaskPair r; r.m0 = false; r.m1 = false;
    int c0 = cell0 + lane, c1 = cell0 + 32 + lane;
    if (mode == 0) {
        const int* mi = (const int*)maskv;
        if (c0 < ncell) r.m0 = mi[c0] != 0;
        if (c1 < ncell) r.m1 = mi[c1] != 0;
    } else if (mode == 1) {
        const unsigned char* mb = (const unsigned char*)maskv;
        if (c0 < ncell) r.m0 = mb[c0] != 0;
        if (c1 < ncell) r.m1 = mb[c1] != 0;
    } else {
        const float* mf = (const float*)maskv;
        if (c0 < ncell) r.m0 = mf[c0] != 0.0f;
        if (c1 < ncell) r.m1 = mf[c1] != 0.0f;
    }
    return r;
}

__device__ __forceinline__ unsigned long long ballotMask(MaskPair mk) {
    unsigned lo = __ballot_sync(0xFFFFFFFFu, mk.m0);
    unsigned hi = __ballot_sync(0xFFFFFFFFu, mk.m1);
    return (unsigned long long)lo | ((unsigned long long)hi << 32);
}

__device__ __forceinline__ void stageTile(
    const float* __restrict__ pred, const float* __restrict__ tcls,
    const float* __restrict__ tbox,
    int cell0, int lane, int ncell,
    unsigned long long wmask, unsigned sbase /* smem u32 addr of buffer */)
{
    // ---- pred: 480 x 16B, unconditional (conf needed even unmasked) ----
    const char* gp = (const char*)(pred + (size_t)cell0 * 30);
    long long predBytes = ((long long)ncell - cell0) * 120;
#pragma unroll
    for (int k = 0; k < 15; k++) {
        int off = (lane + 32 * k) * 16;
        if (off < predBytes)
            asm volatile("cp.async.cg.shared.global [%0], [%1], 16;\n"
                         :: "r"(sbase + (unsigned)off), "l"(gp + off));
    }
    // ---- tcls: 320 x 16B, cell-aligned (5 chunks/cell), mask-predicated ----
    const char* gt = (const char*)(tcls + (size_t)cell0 * 20);
    unsigned tbase = sbase + PRED_FL * 4;
#pragma unroll
    for (int k = 0; k < 10; k++) {
        int chunk = lane + 32 * k;
        int cell = chunk / 5;
        bool need = ((wmask >> cell) & 1ull) && (cell0 + cell) < ncell;
        if (need)
            asm volatile("cp.async.cg.shared.global [%0], [%1], 16;\n"
                         :: "r"(tbase + (unsigned)(chunk * 16)),
                            "l"(gt + chunk * 16));
    }
    // ---- tbox: 64 x 16B, 1 chunk/cell, mask-predicated ----
    const char* gb = (const char*)(tbox + (size_t)cell0 * 4);
    unsigned bbase = sbase + (PRED_FL + TCLS_FL) * 4;
#pragma unroll
    for (int k = 0; k < 2; k++) {
        int cell = lane + 32 * k;
        bool need = ((wmask >> cell) & 1ull) && (cell0 + cell) < ncell;
        if (need)
            asm volatile("cp.async.cg.shared.global [%0], [%1], 16;\n"
                         :: "r"(bbase + (unsigned)(cell * 16)),
                            "l"(gb + cell * 16));
    }
    asm volatile("cp.async.commit_group;\n");
}

__device__ __forceinline__ void computeTile(
    const float* buf, int cell0, int lane, int ncell, MaskPair mk,
    float& s_cls, float& s_noobj, float& s_reg, float& s_cont)
{
    const float* pbuf = buf;
    const float* tbuf = buf + PRED_FL;
    const float4* bbuf = (const float4*)(buf + PRED_FL + TCLS_FL);

#pragma unroll
    for (int half = 0; half < 2; half++) {
        const int r = lane + 32 * half;
        const int c = cell0 + r;
        const bool m = half ? mk.m1 : mk.m0;
        if (c >= ncell) continue;

        const float2* mp2 = (const float2*)(pbuf + r * 30);   // 8B aligned

        if (!m) {
            float cf0 = mp2[2].x;   // float idx 4
            float cf1 = mp2[4].y;   // float idx 9
            s_noobj += cf0 * cf0 + cf1 * cf1;
        } else {
            float pv[10];
#pragma unroll
            for (int j = 0; j < 5; j++) {
                float2 v = mp2[j];
                pv[2 * j]     = v.x;
                pv[2 * j + 1] = v.y;
            }

            // ---- class loss (both operands in smem) ----
            {
                const float4* tc4 = (const float4*)(tbuf + r * 20);
                const float2* mc2 = (const float2*)(pbuf + r * 30 + 10);
                float cls = 0.f;
#pragma unroll
                for (int j = 0; j < 5; j++) {
                    float4 t = tc4[j];
                    float2 a = mc2[2 * j];
                    float2 b = mc2[2 * j + 1];
                    float d0 = t.x - a.x;
                    float d1 = t.y - a.y;
                    float d2 = t.z - b.x;
                    float d3 = t.w - b.y;
                    cls += d0 * d0 + d1 * d1 + d2 * d2 + d3 * d3;
                }
                s_cls += cls;
            }

            // ---- IoU of the two pred boxes vs target ----
            float4 tb = bbuf[r];
            float t_cx = tb.x * S_GRID_INV;
            float t_cy = tb.y * S_GRID_INV;
            float t_x1 = t_cx - 0.5f * tb.z;
            float t_y1 = t_cy - 0.5f * tb.w;
            float t_x2 = t_cx + 0.5f * tb.z;
            float t_y2 = t_cy + 0.5f * tb.w;
            float area_t = (t_x2 - t_x1) * (t_y2 - t_y1);

            float iou[2];
#pragma unroll
            for (int b = 0; b < 2; b++) {
                float px = pv[5 * b + 0] * S_GRID_INV;
                float py = pv[5 * b + 1] * S_GRID_INV;
                float pw = pv[5 * b + 2];
                float ph = pv[5 * b + 3];
                float p_x1 = px - 0.5f * pw;
                float p_y1 = py - 0.5f * ph;
                float p_x2 = px + 0.5f * pw;
                float p_y2 = py + 0.5f * ph;
                float lt_x = fmaxf(t_x1, p_x1);
                float lt_y = fmaxf(t_y1, p_y1);
                float rb_x = fminf(t_x2, p_x2);
                float rb_y = fminf(t_y2, p_y2);
                float w = fmaxf(rb_x - lt_x, 0.0f);
                float h = fmaxf(rb_y - lt_y, 0.0f);
                float inter = w * h;
                float area_p = (p_x2 - p_x1) * (p_y2 - p_y1);
                iou[b] = inter / (area_t + area_p - inter);
            }

            bool sel = iou[1] > iou[0];   // first max wins on tie
            float best_iou = sel ? iou[1] : iou[0];
            float bb_x = sel ? pv[5] : pv[0];
            float bb_y = sel ? pv[6] : pv[1];
            float bb_w = sel ? pv[7] : pv[2];
            float bb_h = sel ? pv[8] : pv[3];
            float bb_c = sel ? pv[9] : pv[4];

            float dx = bb_x - tb.x;
            float dy = bb_y - tb.y;
            float sw = sqrtf(bb_w) - sqrtf(tb.z);
            float sh = sqrtf(bb_h) - sqrtf(tb.w);
            s_reg += dx * dx + dy * dy + sw * sw + sh * sh;

            float dc = best_iou - bb_c;
            s_cont += dc * dc;
        }
    }
}

__global__ void __launch_bounds__(TPB, 1) yolo_fused_kernel(
    const float* __restrict__ pred,
    const float* __restrict__ tbox,
    const float* __restrict__ tcls,
    const void* __restrict__ maskv,
    int ncell, int n_batch, int ntiles, float* __restrict__ out)
{
    const int tid  = threadIdx.x;
    const int warp = tid >> 5;
    const int lane = tid & 31;

    float* buf0 = dynsmem + RED_FL + (warp * 2 + 0) * BUF_FL;
    float* buf1 = dynsmem + RED_FL + (warp * 2 + 1) * BUF_FL;
    unsigned sb0 = (unsigned)__cvta_generic_to_shared(buf0);
    unsigned sb1 = (unsigned)__cvta_generic_to_shared(buf1);

    // ---- mask dtype detection: warp-local ballot over first 32 words ----
    int mode;
    {
        unsigned w0 = ((const unsigned*)maskv)[lane];
        bool gt1 = w0 > 1u;
        bool bad = ((w0 & 0xFFu) > 1u) | (((w0 >> 8) & 0xFFu) > 1u) |
                   (((w0 >> 16) & 0xFFu) > 1u) | ((w0 >> 24) > 1u);
        unsigned bg = __ballot_sync(0xFFFFFFFFu, gt1);
        unsigned bb = __ballot_sync(0xFFFFFFFFu, bad);
        mode = (bg == 0) ? 0 : (bb ? 2 : 1);
    }

    float s_cls = 0.f, s_noobj = 0.f, s_reg = 0.f, s_cont = 0.f;

    // ---- pipelined tile loop (grid-stride over block-tiles) ----
    int tile = blockIdx.x;
    if (tile < ntiles) {
        int cell0 = tile * CPB + warp * CPW;
        MaskPair mk = loadMasks(maskv, mode, cell0, lane, ncell);
        stageTile(pred, tcls, tbox, cell0, lane, ncell, ballotMask(mk),
                  sb0);

        int tileN = tile + gridDim.x;
        MaskPair mkN; mkN.m0 = false; mkN.m1 = false;
        if (tileN < ntiles)
            mkN = loadMasks(maskv, mode, tileN * CPB + warp * CPW, lane, ncell);

        int bufsel = 0;
        MaskPair mkCur = mk;
        while (true) {
            bool hasN = tileN < ntiles;
            unsigned long long wmN = ballotMask(mkN);
            if (hasN) {
                stageTile(pred, tcls, tbox, tileN * CPB + warp * CPW, lane,
                          ncell, wmN, bufsel ? sb0 : sb1);
            }
            int tileNN = tileN + gridDim.x;
            MaskPair mkNN; mkNN.m0 = false; mkNN.m1 = false;
            if (hasN && tileNN < ntiles)
                mkNN = loadMasks(maskv, mode, tileNN * CPB + warp * CPW,
                                 lane, ncell);

            if (hasN) { asm volatile("cp.async.wait_group 1;\n" ::: "memory"); }
            else      { asm volatile("cp.async.wait_group 0;\n" ::: "memory"); }
            __syncwarp();

            computeTile(bufsel ? buf1 : buf0, tile * CPB + warp * CPW, lane,
                        ncell, mkCur, s_cls, s_noobj, s_reg, s_cont);

            if (!hasN) break;
            tile = tileN; mkCur = mkN;
            tileN = tileNN; mkN = mkNN;
            bufsel ^= 1;
        }
    }

    // ---- warp reduction, then block reduction ----
#pragma unroll
    for (int off = 16; off; off >>= 1) {
        s_cls   += __shfl_down_sync(0xFFFFFFFFu, s_cls,   off);
        s_noobj += __shfl_down_sync(0xFFFFFFFFu, s_noobj, off);
        s_reg   += __shfl_down_sync(0xFFFFFFFFu, s_reg,   off);
        s_cont  += __shfl_down_sync(0xFFFFFFFFu, s_cont,  off);
    }
    float* red = dynsmem;                  // [4][NWARP]
    if (lane == 0) {
        red[0 * NWARP + warp] = s_cls;
        red[1 * NWARP + warp] = s_noobj;
        red[2 * NWARP + warp] = s_reg;
        red[3 * NWARP + warp] = s_cont;
    }
    __syncthreads();

    __shared__ bool s_last;
    if (tid == 0) {
        float a0 = 0.f, a1 = 0.f, a2 = 0.f, a3 = 0.f;
#pragma unroll
        for (int w = 0; w < NWARP; w++) {
            a0 += red[0 * NWARP + w];
            a1 += red[1 * NWARP + w];
            a2 += red[2 * NWARP + w];
            a3 += red[3 * NWARP + w];
        }
        atomicAdd(&g_acc[0], (double)a0);
        atomicAdd(&g_acc[1], (double)a1);
        atomicAdd(&g_acc[2], (double)a2);
        atomicAdd(&g_acc[3], (double)a3);

        __threadfence();
        unsigned old = atomicAdd(&g_counter, 1u);
        s_last = (old == gridDim.x - 1);
    }
    __syncthreads();

    if (s_last && tid == 0) {
        double cls   = atomicAdd(&g_acc[0], 0.0);
        double noobj = (double)L_NOOBJ * atomicAdd(&g_acc[1], 0.0);
        double reg   = (double)L_COORD * atomicAdd(&g_acc[2], 0.0);
        double cont  = atomicAdd(&g_acc[3], 0.0);
        double total = (cls + noobj + reg + cont) / (double)n_batch;
        out[0] = (float)total;
        out[1] = (float)reg;
        out[2] = (float)cont;
        out[3] = (float)noobj;
        out[4] = (float)cls;
        g_acc[0] = 0.0; g_acc[1] = 0.0; g_acc[2] = 0.0; g_acc[3] = 0.0;
        __threadfence();
        g_counter = 0u;
    }
}

extern "C" void kernel_launch(void* const* d_in, const int* in_sizes, int n_in,
                              void* d_out, int out_size) {
    // Identify inputs by element count: pred = 30n, tcls = 20n, tbox = 4n, mask = n
    const void* ptrs[4] = {d_in[0], d_in[1], d_in[2], d_in[3]};
    long long sz[4] = {in_sizes[0], in_sizes[1], in_sizes[2], in_sizes[3]};

    int im = 0;
    for (int i = 1; i < 4; i++) if (sz[i] < sz[im]) im = i;
    long long n = sz[im];

    const float* pred = nullptr;
    const float* tbox = nullptr;
    const float* tcls = nullptr;
    const void*  hmask = ptrs[im];
    for (int i = 0; i < 4; i++) {
        if (i == im) continue;
        if (sz[i] == 30 * n) pred = (const float*)ptrs[i];
        else if (sz[i] == 20 * n) tcls = (const float*)ptrs[i];
        else if (sz[i] == 4 * n) tbox = (const float*)ptrs[i];
    }

    int ncell = (int)n;                 // 802816
    int n_batch = ncell / (14 * 14);    // 4096
    int ntiles = (ncell + CPB - 1) / CPB;   // 1568

    cudaFuncSetAttribute(yolo_fused_kernel,
                         cudaFuncAttributeMaxDynamicSharedMemorySize,
                         SMEM_BYTES);
    int dev = 0;
    cudaGetDevice(&dev);
    int nsm = 148;
    cudaDeviceGetAttribute(&nsm, cudaDevAttrMultiProcessorCount, dev);

    int blocks = (ntiles < nsm) ? ntiles : nsm;   // 1 block per SM
    yolo_fused_kernel<<<blocks, TPB, SMEM_BYTES>>>(
        pred, tbox, tcls, hmask, ncell, n_batch, ntiles, (float*)d_out);
}